// round 1
// baseline (speedup 1.0000x reference)
#include <cuda_runtime.h>
#include <cuda_bf16.h>

// MaskSupervisionLoss on GB300.
// Inputs (metadata order):
//   d_in[0]: pred_attn  float32 (32, 8, 256, 256)
//   d_in[1]: gt_masks   float32 (32, 8, 256, 256)
//   d_in[2]: num_objects int32  (32,)
// Output: scalar float32 loss.

#define NB    32          // batch
#define NSLOT 8           // slots (1 bg + 7 fg)
#define HW    65536       // 256*256
#define NCH   16          // chunks per batch
#define CHUNK (HW / NCH)  // 4096
#define TPB   256
#define NV    66          // reduction values per block
#define EPSF  1e-6f

// value layout (per batch):
//  0: bg_inter   1: bg_psum   2: bg_gsum
//  3..9  : psum[fg 0..6]
// 10..16 : gsum[fg 0..6]
// 17..65 : inter[p][g] at 17 + p*7 + g

__device__ float g_scratch[NB * NCH * NV];
__device__ float g_batch[NB * 3];   // {bg_dice, n, best_assignment_dice_sum}

// ---------------------------------------------------------------------------
// Kernel 1: per-(batch, chunk) partial reductions. HBM-bound: reads each of
// the 128MB of input exactly once, coalesced.
// ---------------------------------------------------------------------------
__global__ __launch_bounds__(TPB)
void k_partial(const float* __restrict__ pred, const float* __restrict__ gt) {
    const int b     = blockIdx.y;
    const int chunk = blockIdx.x;
    const int base  = b * NSLOT * HW + chunk * CHUNK;

    float acc[NV];
#pragma unroll
    for (int v = 0; v < NV; v++) acc[v] = 0.f;

    const float* __restrict__ pp = pred + base;
    const float* __restrict__ gg = gt   + base;

#pragma unroll
    for (int k = 0; k < CHUNK / TPB; k++) {          // 16 positions per thread
        const int i = k * TPB + threadIdx.x;
        float p[NSLOT], g[NSLOT];
#pragma unroll
        for (int s = 0; s < NSLOT; s++) {
            p[s] = pp[s * HW + i];
            g[s] = gg[s * HW + i];
        }
        acc[0] = fmaf(p[0], g[0], acc[0]);
        acc[1] += p[0];
        acc[2] += g[0];
#pragma unroll
        for (int s = 1; s < NSLOT; s++) {
            acc[3  + s - 1] += p[s];
            acc[10 + s - 1] += g[s];
        }
#pragma unroll
        for (int pi = 0; pi < 7; pi++)
#pragma unroll
            for (int gi = 0; gi < 7; gi++)
                acc[17 + pi * 7 + gi] = fmaf(p[pi + 1], g[gi + 1], acc[17 + pi * 7 + gi]);
    }

    // warp-level reduce all 66 values
#pragma unroll
    for (int v = 0; v < NV; v++) {
        float x = acc[v];
#pragma unroll
        for (int o = 16; o > 0; o >>= 1)
            x += __shfl_down_sync(0xffffffffu, x, o);
        acc[v] = x;
    }

    __shared__ float sw[TPB / 32][NV];
    const int warp = threadIdx.x >> 5;
    const int lane = threadIdx.x & 31;
    if (lane == 0) {
#pragma unroll
        for (int v = 0; v < NV; v++) sw[warp][v] = acc[v];
    }
    __syncthreads();

    if (threadIdx.x < NV) {
        float s = 0.f;
#pragma unroll
        for (int w = 0; w < TPB / 32; w++) s += sw[w][threadIdx.x];
        g_scratch[(b * NCH + chunk) * NV + threadIdx.x] = s;
    }
}

// ---------------------------------------------------------------------------
// Kernel 2: per-batch — fixed-order chunk reduction, dice matrix, optimal
// assignment via bitmask DP (exact, same optimum as Hungarian; loss depends
// only on the optimal VALUE, so tie-breaking differences are irrelevant).
// ---------------------------------------------------------------------------
__global__ void k_batch(const int* __restrict__ nobj) {
    const int b = blockIdx.x;
    __shared__ float sm[NV];

    if (threadIdx.x < NV) {
        float s = 0.f;
#pragma unroll
        for (int c = 0; c < NCH; c++)
            s += g_scratch[(b * NCH + c) * NV + threadIdx.x];
        sm[threadIdx.x] = s;
    }
    __syncthreads();

    if (threadIdx.x == 0) {
        const float bg_dice = (2.f * sm[0] + EPSF) / (sm[1] + sm[2] + EPSF);

        int n = nobj[b];
        if (n > 7) n = 7;
        if (n < 0) n = 0;

        float dice[49];
#pragma unroll
        for (int p = 0; p < 7; p++)
#pragma unroll
            for (int g = 0; g < 7; g++)
                dice[p * 7 + g] =
                    (2.f * sm[17 + p * 7 + g] + EPSF) / (sm[3 + p] + sm[10 + g] + EPSF);

        float Sb = 0.f;
        if (n > 0) {
            // dp[mask] = max dice-sum assigning gt columns 0..popc(mask)-1 to
            // the pred rows in mask (injectively).
            float dp[128];
            dp[0] = 0.f;
            for (int m = 1; m < 128; m++) {
                const int g = __popc(m) - 1;
                float best = -1e30f;
                if (g < n) {
                    for (int p = 0; p < 7; p++) {
                        if (m & (1 << p)) {
                            const float v = dp[m ^ (1 << p)] + dice[p * 7 + g];
                            if (v > best) best = v;
                        }
                    }
                }
                dp[m] = best;
            }
            Sb = -1e30f;
            for (int m = 1; m < 128; m++)
                if (__popc(m) == n && dp[m] > Sb) Sb = dp[m];
        }

        g_batch[b * 3 + 0] = bg_dice;
        g_batch[b * 3 + 1] = (float)n;
        g_batch[b * 3 + 2] = Sb;
    }
}

// ---------------------------------------------------------------------------
// Kernel 3: final scalar combine.
// ---------------------------------------------------------------------------
__global__ void k_final(float* __restrict__ out) {
    float bg = 0.f, tot = 0.f, ssum = 0.f;
#pragma unroll
    for (int b = 0; b < NB; b++) {
        bg += 1.f - g_batch[b * 3 + 0];
        const float n = g_batch[b * 3 + 1];
        tot += n;
        if (n > 0.f) ssum += g_batch[b * 3 + 2];
    }
    bg *= (1.f / (float)NB);
    const float fg = (tot > 0.f) ? (tot - ssum) / tot : 0.f;
    out[0] = bg + fg;
}

// ---------------------------------------------------------------------------
extern "C" void kernel_launch(void* const* d_in, const int* in_sizes, int n_in,
                              void* d_out, int out_size) {
    const float* pred = (const float*)d_in[0];
    const float* gt   = (const float*)d_in[1];
    const int*   nobj = (const int*)d_in[2];
    float*       out  = (float*)d_out;

    dim3 grid1(NCH, NB);
    k_partial<<<grid1, TPB>>>(pred, gt);
    k_batch<<<NB, 128>>>(nobj);
    k_final<<<1, 1>>>(out);
}